// round 15
// baseline (speedup 1.0000x reference)
#include <cuda_runtime.h>
#include <cuda_fp16.h>
#include <cstdint>

// ============================================================================
// IterativeFixedPoint: z_{k+1} = tanh(W z_k + b + x), z0 = 0, 25 iterations.
// B=32768, F=256. Persistent kernel (148 CTAs), 32-row tiles split into TWO
// independent 16-row sub-tiles, phase-offset by half an iteration so each
// warp's MMA issue gaps absorb the other sub-tile's tanh/pack/STS epilogue.
// ldmatrix + mma.sync.m16n8k16 f16->f32; W fragments register-resident.
// R15: epilogue units front-loaded (ks 0..7) to fill the post-barrier LDSM
// shadow and clear the pre-barrier STS drain; A-fragment LDSM software-
// pipelined (ks+1 prefetch); next tile's x prefetched into L2.
// ============================================================================

#define FEAT       256
#define MSUB       16            // rows per sub-tile
#define NTILES     1024          // 32768 / 32
#define GRID       148
#define NTHREADS   256           // 8 warps, each owns a 32-col slice
#define LOOP_ITERS 22            // k=2 and k=25 peeled; total MMA iters = 24

#define ZS_BYTES   (MSUB * 512)  // 16 rows x 256 f16 = 8 KB per sub-tile
#define WS_BYTES   (256 * 512)   // 128 KB
#define DYNSMEM    (128 + 2 * ZS_BYTES + WS_BYTES)

// ---------------------------------------------------------------------------
// helpers
// ---------------------------------------------------------------------------
static __device__ __forceinline__ uint32_t smem_u32(const void* p) {
    uint32_t a;
    asm("{ .reg .u64 t; cvta.to.shared.u64 t, %1; cvt.u32.u64 %0, t; }"
        : "=r"(a) : "l"(p));
    return a;
}

// row-major K storage, 512B/row (256 f16); 16B chunks XOR-swizzled by (row&7)
static __device__ __forceinline__ uint32_t swz(uint32_t base, int row, int kchunk) {
    return base + (uint32_t)row * 512u + ((uint32_t)(kchunk ^ (row & 7)) << 4);
}

#define LDSM_X4(r0, r1, r2, r3, addr) \
    asm volatile("ldmatrix.sync.aligned.m8n8.x4.shared.b16 {%0,%1,%2,%3}, [%4];" \
                 : "=r"(r0), "=r"(r1), "=r"(r2), "=r"(r3) : "r"(addr))

#define MMA16816(d, a, b) \
    asm volatile("mma.sync.aligned.m16n8k16.row.col.f32.f16.f16.f32 " \
                 "{%0,%1,%2,%3}, {%4,%5,%6,%7}, {%8,%9}, {%0,%1,%2,%3};" \
                 : "+f"((d)[0]), "+f"((d)[1]), "+f"((d)[2]), "+f"((d)[3]) \
                 : "r"((a)[0]), "r"((a)[1]), "r"((a)[2]), "r"((a)[3]), \
                   "r"((b)[0]), "r"((b)[1]))

#define MMA16816_C(d, a, b, c) \
    asm volatile("mma.sync.aligned.m16n8k16.row.col.f32.f16.f16.f32 " \
                 "{%0,%1,%2,%3}, {%4,%5,%6,%7}, {%8,%9}, {%10,%11,%12,%13};" \
                 : "=f"((d)[0]), "=f"((d)[1]), "=f"((d)[2]), "=f"((d)[3]) \
                 : "r"((a)[0]), "r"((a)[1]), "r"((a)[2]), "r"((a)[3]), \
                   "r"((b)[0]), "r"((b)[1]), \
                   "f"((c)[0]), "f"((c)[1]), "f"((c)[2]), "f"((c)[3]))

// exact tanh: 1 - 2/(exp2(2u*log2e)+1); ~1e-6 rel err, exact saturation
static __device__ __forceinline__ float tanh_exact(float u) {
    float e;
    asm("ex2.approx.f32 %0, %1;" : "=f"(e) : "f"(u * 2.885390081777927f));
    float r;
    asm("rcp.approx.f32 %0, %1;" : "=f"(r) : "f"(e + 1.0f));
    return fmaf(-2.0f, r, 1.0f);
}

static __device__ __forceinline__ uint32_t tanh_h2(uint32_t u) {
    uint32_t r;
    asm("tanh.approx.f16x2 %0, %1;" : "=r"(r) : "r"(u));
    return r;
}

static __device__ __forceinline__ uint32_t f2h2(float a, float b) {
    __half2 h = __floats2half2_rn(a, b);   // .x = a = low half = even column
    return *reinterpret_cast<uint32_t*>(&h);
}

#define STSB32(addr, v) \
    asm volatile("st.shared.b32 [%0], %1;" :: "r"(addr), "r"(v) : "memory")

// one epilogue unit e in [0,8): z[dst] = tanh~(src) for (hh, nb) = (e>>2, e&3)
static __device__ __forceinline__ void epi_unit(
    int e, const float (&src)[4][4], uint32_t dst,
    int rowq, int colq, int C0)
{
    const int hh  = e >> 2, nb = e & 3;
    const int row = hh * 8 + rowq;
    const int bcol = (C0 + colq) * 2 + nb * 16;
    uint32_t v = tanh_h2(f2h2(src[nb][2 * hh], src[nb][2 * hh + 1]));
    STSB32(swz(dst, row, bcol >> 4) + (bcol & 15), v);
}

// full 8-unit epilogue (prologue use, no MMA to hide under)
static __device__ __forceinline__ void epi8(
    const float (&src)[4][4], uint32_t dst, int rowq, int colq, int C0)
{
#pragma unroll
    for (int e = 0; e < 8; e++) epi_unit(e, src, dst, rowq, colq, C0);
}

// half-iteration: d = W * z(zbuf) + c for one 16-row sub-tile. Epilogue of the
// OTHER sub-tile (src -> dstbuf) is front-loaded at ks 0..7 to fill the
// post-barrier LDSM shadow; A-fragment LDSM is pipelined one ks ahead.
template <int EPI>
static __device__ __forceinline__ void half_step(
    float (&d)[4][4], uint32_t zbuf, const float (&c)[4][4],
    const float (&src)[4][4], uint32_t dstbuf,
    const uint32_t (&Wb)[16][4][2],
    int arow, int akc, int rowq, int colq, int C0)
{
    uint32_t a0[4], a1[4];
    LDSM_X4(a0[0], a0[1], a0[2], a0[3], swz(zbuf, arow, akc));
#pragma unroll
    for (int ks = 0; ks < 16; ks++) {
        uint32_t* a  = (ks & 1) ? a1 : a0;
        uint32_t* an = (ks & 1) ? a0 : a1;
        if (ks < 15)
            LDSM_X4(an[0], an[1], an[2], an[3],
                    swz(zbuf, arow, (ks + 1) * 2 + akc));
        if (EPI && ks < 8)
            epi_unit(ks, src, dstbuf, rowq, colq, C0);
        if (ks == 0) {
#pragma unroll
            for (int nb = 0; nb < 4; nb++)
                MMA16816_C(d[nb], a, Wb[0][nb], c[nb]);
        } else {
#pragma unroll
            for (int nb = 0; nb < 4; nb++)
                MMA16816(d[nb], a, Wb[ks][nb]);
        }
    }
}

// c = x + b in fragment layout for one 16-row sub-tile
static __device__ __forceinline__ void load_c(
    float (&c)[4][4], const float* gx, const float2 (&bp)[4],
    int gRowBase, int rowq, int colq, int C0)
{
#pragma unroll
    for (int hh = 0; hh < 2; hh++) {
        const float2* xr = reinterpret_cast<const float2*>(
            gx + (size_t)(gRowBase + hh * 8 + rowq) * FEAT);
#pragma unroll
        for (int nb = 0; nb < 4; nb++) {
            float2 xv = xr[(C0 + nb * 8 + colq) >> 1];
            c[nb][2 * hh + 0] = xv.x + bp[nb].x;
            c[nb][2 * hh + 1] = xv.y + bp[nb].y;
        }
    }
}

// final exact epilogue: gout = tanh(d), f32
static __device__ __forceinline__ void final_store(
    const float (&d)[4][4], float* gout, int gRowBase,
    int rowq, int colq, int C0)
{
#pragma unroll
    for (int hh = 0; hh < 2; hh++) {
        int row = gRowBase + hh * 8 + rowq;
        float2* o = reinterpret_cast<float2*>(gout + (size_t)row * FEAT);
#pragma unroll
        for (int nb = 0; nb < 4; nb++)
            o[(C0 + nb * 8 + colq) >> 1] =
                make_float2(tanh_exact(d[nb][2 * hh]),
                            tanh_exact(d[nb][2 * hh + 1]));
    }
}

// ---------------------------------------------------------------------------
// kernel
// ---------------------------------------------------------------------------
__global__ void __launch_bounds__(NTHREADS, 1)
IterativeFixedPoint_kernel(const float* __restrict__ gx,
                           const float* __restrict__ gW,
                           const float* __restrict__ gb,
                           float* __restrict__ gout)
{
    extern __shared__ char smraw[];
    const uint32_t base = (smem_u32(smraw) + 127u) & ~127u;
    const uint32_t zsA = base;                  // sub-tile A z (16x256 f16)
    const uint32_t zsB = base + ZS_BYTES;       // sub-tile B z
    const uint32_t ws  = base + 2 * ZS_BYTES;   // W (256x256 f16, 128KB)

    const int tid  = threadIdx.x;
    const int lane = tid & 31;
    const int warp = tid >> 5;
    const int C0   = warp * 32;                 // warp col slice
    const int rowq = lane >> 2;
    const int colq = (lane & 3) * 2;

    const int gA   = lane >> 3;
    const int arow = ((gA & 1) * 8) + (lane & 7);
    const int akc  = (gA >> 1);
    const int brow = ((gA >> 1) * 8) + (lane & 7);
    const int bkc  = (gA & 1);

    // ---- W -> smem f16 once (thread t owns W row t)
    {
        const float4* wr = reinterpret_cast<const float4*>(gW + (size_t)tid * FEAT);
#pragma unroll
        for (int q = 0; q < 32; q++) {
            float4 a  = wr[2 * q];
            float4 a2 = wr[2 * q + 1];
            uint32_t v0 = f2h2(a.x,  a.y);
            uint32_t v1 = f2h2(a.z,  a.w);
            uint32_t v2 = f2h2(a2.x, a2.y);
            uint32_t v3 = f2h2(a2.z, a2.w);
            asm volatile("st.shared.v4.b32 [%0], {%1,%2,%3,%4};"
                         :: "r"(swz(ws, tid, q)), "r"(v0), "r"(v1), "r"(v2), "r"(v3)
                         : "memory");
        }
    }
    __syncthreads();

    // ---- W fragments -> registers, once per CTA
    uint32_t Wb[16][4][2];
#pragma unroll
    for (int ks = 0; ks < 16; ks++)
#pragma unroll
        for (int np = 0; np < 2; np++)
            LDSM_X4(Wb[ks][2 * np][0],     Wb[ks][2 * np][1],
                    Wb[ks][2 * np + 1][0], Wb[ks][2 * np + 1][1],
                    swz(ws, C0 + np * 16 + brow, ks * 2 + bkc));

    // ---- b fragment (constant across tiles)
    float2 bp[4];
#pragma unroll
    for (int nb = 0; nb < 4; nb++)
        bp[nb] = *reinterpret_cast<const float2*>(gb + C0 + nb * 8 + colq);

    // ---- persistent tile loop (1024 tiles of 32 rows = 2 sub-tiles)
    for (int tile = blockIdx.x; tile < NTILES; tile += GRID) {
        const int gRow0 = tile * 32;

        float cA[4][4], cB[4][4];
        load_c(cA, gx, bp, gRow0,      rowq, colq, C0);
        load_c(cB, gx, bp, gRow0 + 16, rowq, colq, C0);

        // iter 1 (A): zA1 = tanh~(cA)
        epi8(cA, zsA, rowq, colq, C0);
        __syncthreads();

        // prefetch next tile's x slab (32KB = 256 x 128B lines) into L2
        if (tile + GRID < NTILES) {
            const char* pf = reinterpret_cast<const char*>(
                gx + (size_t)(tile + GRID) * 32 * FEAT) + tid * 128;
            asm volatile("prefetch.global.L2 [%0];" :: "l"(pf));
        }

        float dA[4][4], dB[4][4];

        // k = 2: A's MMA hides B's iter-1 epilogue (zB1 = tanh~(cB))
        half_step<1>(dA, zsA, cA, cB, zsB, Wb, arow, akc, rowq, colq, C0);
        __syncthreads();
        half_step<1>(dB, zsB, cB, dA, zsA, Wb, arow, akc, rowq, colq, C0);
        __syncthreads();

        // k = 3..24
#pragma unroll 1
        for (int k = 0; k < LOOP_ITERS; k++) {
            half_step<1>(dA, zsA, cA, dB, zsB, Wb, arow, akc, rowq, colq, C0);
            __syncthreads();
            half_step<1>(dB, zsB, cB, dA, zsA, Wb, arow, akc, rowq, colq, C0);
            __syncthreads();
        }

        // k = 25: last B half has no smem epilogue; finals are exact f32
        half_step<1>(dA, zsA, cA, dB, zsB, Wb, arow, akc, rowq, colq, C0);
        __syncthreads();
        half_step<0>(dB, zsB, cB, dB, zsB, Wb, arow, akc, rowq, colq, C0);

        final_store(dA, gout, gRow0,      rowq, colq, C0);
        final_store(dB, gout, gRow0 + 16, rowq, colq, C0);
        __syncthreads();   // z buffers reused by next tile's prologue
    }
}

// ---------------------------------------------------------------------------
// launch
// ---------------------------------------------------------------------------
extern "C" void kernel_launch(void* const* d_in, const int* in_sizes, int n_in,
                              void* d_out, int out_size)
{
    // identify inputs by size (x: 8388608, W: 65536, b: 256)
    const float* x = nullptr;
    const float* W = nullptr;
    const float* b = nullptr;
    for (int i = 0; i < n_in; i++) {
        if (in_sizes[i] == FEAT)             b = (const float*)d_in[i];
        else if (in_sizes[i] == FEAT * FEAT) W = (const float*)d_in[i];
        else                                 x = (const float*)d_in[i];
    }

    cudaFuncSetAttribute(IterativeFixedPoint_kernel,
                         cudaFuncAttributeMaxDynamicSharedMemorySize, DYNSMEM);

    IterativeFixedPoint_kernel<<<GRID, NTHREADS, DYNSMEM>>>(
        x, W, b, (float*)d_out);
}